// round 2
// baseline (speedup 1.0000x reference)
#include <cuda_runtime.h>

// Fused: bilinear 2x upsample -> leaky_relu(0.01) -> bilinear 0.5x downsample
// collapses to a 3x3 stencil on the input (see derivation in commit message).
//
// x, out: (16, 128, 128, 128) fp32 NHWC. Channels (128 fp32 = 32 float4) are
// innermost -> vectorize channels across 32 threads, 8 j-strips of 16 pixels
// per 256-thread block, one block per (batch, output row).

constexpr int H  = 128;
constexpr int W  = 128;
constexpr int C4 = 32;    // 128 channels / 4 (float4 groups)
constexpr int STRIP = 16; // output pixels per thread (W / 8 strips)

__device__ __forceinline__ float4 f4add(float4 a, float4 b) {
    return make_float4(a.x + b.x, a.y + b.y, a.z + b.z, a.w + b.w);
}

// leaky_relu: max(u, 0.01*u) — exact for both signs, 2 instr/lane
__device__ __forceinline__ float4 f4act(float4 u) {
    return make_float4(fmaxf(u.x, 0.01f * u.x),
                       fmaxf(u.y, 0.01f * u.y),
                       fmaxf(u.z, 0.01f * u.z),
                       fmaxf(u.w, 0.01f * u.w));
}

// Horizontal pair: L = 0.25*a + 0.75*b ; R = 0.75*b + 0.25*c  (t = 0.75*b shared)
__device__ __forceinline__ void hlerp(const float4& a, const float4& b, const float4& c,
                                      float4& L, float4& R) {
    float tx = 0.75f * b.x, ty = 0.75f * b.y, tz = 0.75f * b.z, tw = 0.75f * b.w;
    L = make_float4(fmaf(a.x, 0.25f, tx), fmaf(a.y, 0.25f, ty),
                    fmaf(a.z, 0.25f, tz), fmaf(a.w, 0.25f, tw));
    R = make_float4(fmaf(c.x, 0.25f, tx), fmaf(c.y, 0.25f, ty),
                    fmaf(c.z, 0.25f, tz), fmaf(c.w, 0.25f, tw));
}

// Vertical pair from 3 row values sharing the middle: U0 = 0.25*v0 + 0.75*v1,
// U1 = 0.75*v1 + 0.25*v2  (t = 0.75*v1 shared)
__device__ __forceinline__ void vlerp(const float4& v0, const float4& v1, const float4& v2,
                                      float4& U0, float4& U1) {
    float tx = 0.75f * v1.x, ty = 0.75f * v1.y, tz = 0.75f * v1.z, tw = 0.75f * v1.w;
    U0 = make_float4(fmaf(v0.x, 0.25f, tx), fmaf(v0.y, 0.25f, ty),
                     fmaf(v0.z, 0.25f, tz), fmaf(v0.w, 0.25f, tw));
    U1 = make_float4(fmaf(v2.x, 0.25f, tx), fmaf(v2.y, 0.25f, ty),
                     fmaf(v2.z, 0.25f, tz), fmaf(v2.w, 0.25f, tw));
}

__global__ __launch_bounds__(256, 2)
void activation_filter_kernel(const float4* __restrict__ x, float4* __restrict__ out) {
    const int i   = blockIdx.x;       // output row
    const int b   = blockIdx.y;       // batch
    const int tid = threadIdx.x;
    const int c4    = tid & 31;       // float4 channel group
    const int strip = tid >> 5;       // 0..7
    const int j0    = strip * STRIP;

    const int im = (i > 0)     ? i - 1 : 0;
    const int ip = (i < H - 1) ? i + 1 : H - 1;

    const size_t img = (size_t)b * H * W * C4;
    const float4* __restrict__ rm = x + img + (size_t)im * W * C4 + c4;
    const float4* __restrict__ rc = x + img + (size_t)i  * W * C4 + c4;
    const float4* __restrict__ rp = x + img + (size_t)ip * W * C4 + c4;
    float4* __restrict__ po = out + img + (size_t)i * W * C4 + c4;

    // Sliding window: a* = col j-1, b* = col j (rows m/c/p)
    const int jm = (j0 > 0) ? j0 - 1 : 0;
    float4 a0 = rm[(size_t)jm * C4], b0 = rm[(size_t)j0 * C4];
    float4 a1 = rc[(size_t)jm * C4], b1 = rc[(size_t)j0 * C4];
    float4 a2 = rp[(size_t)jm * C4], b2 = rp[(size_t)j0 * C4];

    #pragma unroll 2
    for (int j = j0; j < j0 + STRIP; ++j) {
        const int jn = (j < W - 1) ? j + 1 : W - 1;
        float4 c0 = rm[(size_t)jn * C4];
        float4 c1 = rc[(size_t)jn * C4];
        float4 c2 = rp[(size_t)jn * C4];

        float4 L0, R0, L1, R1, L2, R2;
        hlerp(a0, b0, c0, L0, R0);
        hlerp(a1, b1, c1, L1, R1);
        hlerp(a2, b2, c2, L2, R2);

        float4 u00, u10, u01, u11;
        vlerp(L0, L1, L2, u00, u10);
        vlerp(R0, R1, R2, u01, u11);

        float4 s = f4add(f4add(f4act(u00), f4act(u01)),
                         f4add(f4act(u10), f4act(u11)));
        po[(size_t)j * C4] = make_float4(0.25f * s.x, 0.25f * s.y,
                                         0.25f * s.z, 0.25f * s.w);

        a0 = b0; b0 = c0;
        a1 = b1; b1 = c1;
        a2 = b2; b2 = c2;
    }
}

extern "C" void kernel_launch(void* const* d_in, const int* in_sizes, int n_in,
                              void* d_out, int out_size) {
    const float4* x = (const float4*)d_in[0];
    float4* out = (float4*)d_out;
    dim3 grid(H, 16);   // (output row, batch)
    activation_filter_kernel<<<grid, 256>>>(x, out);
}

// round 3
// speedup vs baseline: 1.1123x; 1.1123x over previous
#include <cuda_runtime.h>

// Fused bilinear 2x up -> leaky_relu(0.01) -> bilinear 0.5x down == 3x3 stencil.
// x, out: (16, 128, 128, 128) fp32 NHWC.
//
// R2 changes vs R1 (59.3us kernel, alu=25.9%, occ=22.5%, issue=53%):
//  - all 32-bit indexing, loads/stores via pointer bumps with immediate offsets
//  - column clamp peeled out of the hot loop (warp-uniform final iteration)
//  - __launch_bounds__(256,3) for 24 warps/SM
//  - __stcs streaming output stores (preserve L2 for vertically-reused input)

constexpr int H  = 128;
constexpr int W  = 128;
constexpr int C4 = 32;    // 128 channels / 4
constexpr int STRIP = 16; // output pixels per thread

__device__ __forceinline__ float4 f4add(float4 a, float4 b) {
    return make_float4(a.x + b.x, a.y + b.y, a.z + b.z, a.w + b.w);
}

__device__ __forceinline__ float4 f4act(float4 u) {  // leaky_relu = max(u, 0.01u)
    return make_float4(fmaxf(u.x, 0.01f * u.x),
                       fmaxf(u.y, 0.01f * u.y),
                       fmaxf(u.z, 0.01f * u.z),
                       fmaxf(u.w, 0.01f * u.w));
}

// L = 0.25*a + 0.75*b ; R = 0.75*b + 0.25*c  (t = 0.75*b shared)
__device__ __forceinline__ void hlerp(const float4& a, const float4& b, const float4& c,
                                      float4& L, float4& R) {
    float tx = 0.75f * b.x, ty = 0.75f * b.y, tz = 0.75f * b.z, tw = 0.75f * b.w;
    L = make_float4(fmaf(a.x, 0.25f, tx), fmaf(a.y, 0.25f, ty),
                    fmaf(a.z, 0.25f, tz), fmaf(a.w, 0.25f, tw));
    R = make_float4(fmaf(c.x, 0.25f, tx), fmaf(c.y, 0.25f, ty),
                    fmaf(c.z, 0.25f, tz), fmaf(c.w, 0.25f, tw));
}

__device__ __forceinline__ void vlerp(const float4& v0, const float4& v1, const float4& v2,
                                      float4& U0, float4& U1) {
    float tx = 0.75f * v1.x, ty = 0.75f * v1.y, tz = 0.75f * v1.z, tw = 0.75f * v1.w;
    U0 = make_float4(fmaf(v0.x, 0.25f, tx), fmaf(v0.y, 0.25f, ty),
                     fmaf(v0.z, 0.25f, tz), fmaf(v0.w, 0.25f, tw));
    U1 = make_float4(fmaf(v2.x, 0.25f, tx), fmaf(v2.y, 0.25f, ty),
                     fmaf(v2.z, 0.25f, tz), fmaf(v2.w, 0.25f, tw));
}

// Full 3x3 stencil body: 9 window values -> one output float4
__device__ __forceinline__ float4 stencil(
    const float4& a0, const float4& b0, const float4& c0,
    const float4& a1, const float4& b1, const float4& c1,
    const float4& a2, const float4& b2, const float4& c2) {
    float4 L0, R0, L1, R1, L2, R2;
    hlerp(a0, b0, c0, L0, R0);
    hlerp(a1, b1, c1, L1, R1);
    hlerp(a2, b2, c2, L2, R2);
    float4 u00, u10, u01, u11;
    vlerp(L0, L1, L2, u00, u10);
    vlerp(R0, R1, R2, u01, u11);
    float4 s = f4add(f4add(f4act(u00), f4act(u01)),
                     f4add(f4act(u10), f4act(u11)));
    return make_float4(0.25f * s.x, 0.25f * s.y, 0.25f * s.z, 0.25f * s.w);
}

__global__ __launch_bounds__(256, 3)
void activation_filter_kernel(const float4* __restrict__ x, float4* __restrict__ out) {
    const int i   = blockIdx.x;        // output row
    const int b   = blockIdx.y;        // batch
    const int tid = threadIdx.x;
    const int c4    = tid & 31;
    const int strip = tid >> 5;        // 0..7, warp-uniform
    const int j0    = strip * STRIP;

    const int im = (i > 0)     ? i - 1 : 0;
    const int ip = (i < H - 1) ? i + 1 : H - 1;

    const int img  = b * (H * W * C4);          // max 8.4M float4, fits int
    const int base = j0 * C4 + c4;
    const float4* __restrict__ pm = x + img + im * (W * C4) + base;
    const float4* __restrict__ pc = x + img + i  * (W * C4) + base;
    const float4* __restrict__ pp = x + img + ip * (W * C4) + base;
    float4* __restrict__ po = out + img + i * (W * C4) + base;

    // window prologue: a = col j-1 (clamped, warp-uniform offset), b = col j
    const int offA = (j0 > 0) ? -C4 : 0;
    float4 a0 = pm[offA], b0 = pm[0];
    float4 a1 = pc[offA], b1 = pc[0];
    float4 a2 = pp[offA], b2 = pp[0];

    #pragma unroll 5
    for (int s = 0; s < STRIP - 1; ++s) {
        float4 c0 = pm[C4];
        float4 c1 = pc[C4];
        float4 c2 = pp[C4];

        float4 r = stencil(a0, b0, c0, a1, b1, c1, a2, b2, c2);
        __stcs(po, r);

        a0 = b0; b0 = c0;
        a1 = b1; b1 = c1;
        a2 = b2; b2 = c2;
        pm += C4; pc += C4; pp += C4; po += C4;
    }

    // final pixel of the strip: only strip 7 needs the right-edge clamp
    float4 c0, c1, c2;
    if (j0 + STRIP < W) {              // warp-uniform branch
        c0 = pm[C4]; c1 = pc[C4]; c2 = pp[C4];
    } else {
        c0 = b0; c1 = b1; c2 = b2;
    }
    __stcs(po, stencil(a0, b0, c0, a1, b1, c1, a2, b2, c2));
}

extern "C" void kernel_launch(void* const* d_in, const int* in_sizes, int n_in,
                              void* d_out, int out_size) {
    const float4* x = (const float4*)d_in[0];
    float4* out = (float4*)d_out;
    dim3 grid(H, 16);   // (output row, batch)
    activation_filter_kernel<<<grid, 256>>>(x, out);
}